// round 2
// baseline (speedup 1.0000x reference)
#include <cuda_runtime.h>

#define IN_H 4096
#define IN_W 4096
#define KH 16
#define KW 16
#define OUT_H 4081
#define OUT_W 4081

#define TILE_ROWS 64       // output rows per block
#define TILE_COLS 128      // output cols per block
#define TY 2               // output rows per thread
#define TX 16              // output cols per thread
#define PITCH 148          // smem row pitch (floats), mult of 4, breaks bank aliasing
#define SX_ROWS (TILE_ROWS + KH - 1)   // 79
#define SX_C4 36           // float4 per smem row (144 floats >= 143 needed)

__global__ __launch_bounds__(256, 2)
void conv2d_k16_kernel(const float* __restrict__ x,
                       const float* __restrict__ w,
                       const float* __restrict__ bias,
                       float* __restrict__ out)
{
    __shared__ float sx[SX_ROWS * PITCH];
    __shared__ float sw[KH * KW];

    const int tid  = threadIdx.x;
    const int col0 = blockIdx.x * TILE_COLS;
    const int row0 = blockIdx.y * TILE_ROWS;

    // ---- load weights (256 floats) ----
    sw[tid] = w[tid];

    // ---- stage input tile: 79 rows x 143 cols (pitch 148), zero-padded OOB ----
    for (int idx = tid; idx < SX_ROWS * SX_C4; idx += 256) {
        const int r  = idx / SX_C4;
        const int c4 = idx - r * SX_C4;
        const int gr = row0 + r;
        const int gc = col0 + c4 * 4;
        float4 v = make_float4(0.f, 0.f, 0.f, 0.f);
        if (gr < IN_H) {
            if (gc + 3 < IN_W) {
                v = *reinterpret_cast<const float4*>(x + (size_t)gr * IN_W + gc);
            } else {
                float t[4] = {0.f, 0.f, 0.f, 0.f};
                #pragma unroll
                for (int k = 0; k < 4; ++k)
                    if (gc + k < IN_W) t[k] = x[(size_t)gr * IN_W + gc + k];
                v = make_float4(t[0], t[1], t[2], t[3]);
            }
        }
        *reinterpret_cast<float4*>(sx + r * PITCH + c4 * 4) = v;
    }
    __syncthreads();

    // ---- per-thread tile: TY=2 rows x TX=16 cols ----
    const int tx   = tid & 7;      // 0..7  -> col group
    const int ty   = tid >> 3;     // 0..31 -> row group
    const int ocol = tx * TX;      // tile-local output col base
    const int orow = ty * TY;      // tile-local output row base

    float acc0[TX], acc1[TX];
    #pragma unroll
    for (int i = 0; i < TX; ++i) { acc0[i] = 0.f; acc1[i] = 0.f; }

    // rolling 2-row register buffer, 32 floats (cols ocol..ocol+31) each
    float buf[2][32];

    // preload row orow (used by p=0 for acc0)
    {
        const float* src = sx + orow * PITCH + ocol;
        #pragma unroll
        for (int k = 0; k < 8; ++k) {
            float4 v = *reinterpret_cast<const float4*>(src + k * 4);
            buf[0][k*4+0] = v.x; buf[0][k*4+1] = v.y;
            buf[0][k*4+2] = v.z; buf[0][k*4+3] = v.w;
        }
    }

    #pragma unroll 2
    for (int p = 0; p < KH; ++p) {
        // load row orow + p + 1 into the buffer not used as "row p"
        {
            const int nb = (p + 1) & 1;
            const float* src = sx + (orow + p + 1) * PITCH + ocol;
            #pragma unroll
            for (int k = 0; k < 8; ++k) {
                float4 v = *reinterpret_cast<const float4*>(src + k * 4);
                buf[nb][k*4+0] = v.x; buf[nb][k*4+1] = v.y;
                buf[nb][k*4+2] = v.z; buf[nb][k*4+3] = v.w;
            }
        }
        // weight row p
        float wr[KW];
        {
            const float* wsrc = sw + p * KW;
            #pragma unroll
            for (int k = 0; k < 4; ++k) {
                float4 v = *reinterpret_cast<const float4*>(wsrc + k * 4);
                wr[k*4+0] = v.x; wr[k*4+1] = v.y;
                wr[k*4+2] = v.z; wr[k*4+3] = v.w;
            }
        }
        const int b0 = p & 1;        // holds input row orow+p   (for output row 0)
        const int b1 = (p + 1) & 1;  // holds input row orow+p+1 (for output row 1)
        #pragma unroll
        for (int q = 0; q < KW; ++q) {
            const float wv = wr[q];
            #pragma unroll
            for (int c = 0; c < TX; ++c) {
                acc0[c] = fmaf(buf[b0][c + q], wv, acc0[c]);
                acc1[c] = fmaf(buf[b1][c + q], wv, acc1[c]);
            }
        }
    }

    // ---- store with bias ----
    const float b = bias[0];
    const int gor = row0 + orow;
    const int goc = col0 + ocol;

    if (gor < OUT_H) {
        float* orow0 = out + (size_t)gor * OUT_W + goc;
        #pragma unroll
        for (int c = 0; c < TX; ++c)
            if (goc + c < OUT_W) orow0[c] = acc0[c] + b;
    }
    if (gor + 1 < OUT_H) {
        float* orow1 = out + (size_t)(gor + 1) * OUT_W + goc;
        #pragma unroll
        for (int c = 0; c < TX; ++c)
            if (goc + c < OUT_W) orow1[c] = acc1[c] + b;
    }
}

extern "C" void kernel_launch(void* const* d_in, const int* in_sizes, int n_in,
                              void* d_out, int out_size)
{
    (void)in_sizes; (void)n_in; (void)out_size;
    const float* x    = (const float*)d_in[0];
    const float* w    = (const float*)d_in[1];
    const float* bias = (const float*)d_in[2];
    float* out        = (float*)d_out;

    dim3 grid((OUT_W + TILE_COLS - 1) / TILE_COLS,   // 32
              (OUT_H + TILE_ROWS - 1) / TILE_ROWS);  // 64
    conv2d_k16_kernel<<<grid, 256>>>(x, w, bias, out);
}